// round 15
// baseline (speedup 1.0000x reference)
#include <cuda_runtime.h>
#include <math.h>

#define D 128
#define HD 1024
#define H 8
#define NCIR 585
#define NDIS 88
#define ECC 20000
#define EDD 3000
#define BUCK 128
#define GE0 79
#define GE1 12
#define GEDGE (GE0 + GE1)   // 91
#define GT0 37
#define GT1 6
#define GTILE (GT0 + GT1)   // 43
#define GPREP 86
#define RB 54               // reset blocks in k_final
#define NT (NCIR + NDIS)    // 673
#define NPREP 6160          // 4096 va + 16 cvec + 2048 weff
#define FULL 0xffffffffu

__device__ __align__(16) float g_scratch[1600000];

struct BP {
    const float *x, *mat;
    const int *edges;
    const float *gb1, *ab, *gb2, *cw, *cb;
    const float *asrc, *adst, *aedge, *awe;
    const float *gw1, *aw, *gw2;
    float *fea;
    int N, E;
    float *degw, *h, *f1, *g, *an_src, *an_dst, *att, *f2, *cvec, *ewsum;
    float *vsrc, *vdst, *weff, *eew;
    int *cnt, *esrc;
};
struct Pair { BP b[2]; };

static inline int pad4(int n) { return (n + 3) & ~3; }

__device__ __forceinline__ float4 ld4(const float* p) { return *(const float4*)p; }
__device__ __forceinline__ float wsum(float v) {
    #pragma unroll
    for (int o = 16; o; o >>= 1) v += __shfl_xor_sync(FULL, v, o);
    return v;
}

// ---- GEMM tile (K=128): C[rb:rb+16, cb:cb+128] = A[*,128] @ W[128,ncols] ----
__device__ void gemm_tile(float* sA, int tid, const float* __restrict__ A,
                          const float* __restrict__ W, float* __restrict__ C,
                          int M, int ncols, int rb, int cb, bool reluA) {
    #pragma unroll
    for (int q = 0; q < 8; q++) {
        int idx = q * 256 + tid;
        int r = idx >> 7, k = idx & 127;
        float v = (rb + r < M) ? A[(rb + r) * 128 + k] : 0.f;
        sA[idx] = reluA ? fmaxf(v, 0.f) : v;
    }
    __syncthreads();
    int col = cb + (tid & 127);
    int r0 = (tid >> 7) << 3;
    const float4* sA4 = (const float4*)sA;
    float acc[8] = {0.f, 0.f, 0.f, 0.f, 0.f, 0.f, 0.f, 0.f};
    #pragma unroll 4
    for (int k4 = 0; k4 < 32; k4++) {
        float w0 = W[(k4 * 4 + 0) * ncols + col];
        float w1 = W[(k4 * 4 + 1) * ncols + col];
        float w2 = W[(k4 * 4 + 2) * ncols + col];
        float w3 = W[(k4 * 4 + 3) * ncols + col];
        #pragma unroll
        for (int r = 0; r < 8; r++) {
            float4 a = sA4[(r0 + r) * 32 + k4];
            acc[r] = fmaf(a.x, w0, fmaf(a.y, w1, fmaf(a.z, w2, fmaf(a.w, w3, acc[r]))));
        }
    }
    #pragma unroll
    for (int r = 0; r < 8; r++)
        if (rb + r0 + r < M) C[(rb + r0 + r) * ncols + col] = acc[r];
}

// ---- prep warp tasks: va dots | cvec | W_eff build (column-major, coalesced) ----
__device__ void prep_warp(const Pair& P, int tt, int lane) {
    if (tt < 4096) {
        int br = tt >> 11; int r = tt & 2047;
        int type = r >> 10; r &= 1023;
        int hh = r >> 7; int k = r & 127;
        const BP& bp = P.b[br];
        const float* avec = type ? bp.adst : bp.asrc;
        float* vout = type ? bp.vdst : bp.vsrc;
        float4 w4 = ld4(bp.aw + k * HD + hh * D + lane * 4);
        float4 a4 = ld4(avec + hh * D + lane * 4);
        float s = wsum(w4.x * a4.x + w4.y * a4.y + w4.z * a4.z + w4.w * a4.w);
        if (lane == 0) vout[hh * D + k] = s;
    } else if (tt < 4112) {
        int r = tt - 4096;
        int br = r >> 3; int hh = r & 7;
        const BP& bp = P.b[br];
        float4 a = ld4(bp.awe + hh * D + lane * 4);
        float4 e = ld4(bp.aedge + hh * D + lane * 4);
        float s = wsum(a.x * e.x + a.y * e.y + a.z * e.z + a.w * e.w);
        if (lane == 0) bp.cvec[hh] = s;
    } else {
        int r = tt - 4112;                 // 0..2047
        int br = r >> 10; r &= 1023;
        int hh = r >> 7; int k = r & 127;
        const BP& bp = P.b[br];
        float4 v = ld4(bp.aw + k * HD + hh * D + lane * 4);
        v.x *= 0.125f; v.y *= 0.125f; v.z *= 0.125f; v.w *= 0.125f;
        ((float4*)(bp.weff + (hh * 128 + k) * 128))[lane] = v;
    }
}

// ============ K1: edge->buckets/deg/ewsum || GEMM1 || prep ============
__global__ void k_phase1(Pair P) {
    __shared__ __align__(16) float sA[2048];
    int tid = threadIdx.x, lane = tid & 31, wid = tid >> 5;
    int b = blockIdx.x;
    if (b < GEDGE) {
        int br = b >= GE0;
        const BP& bp = P.b[br];
        int e = (br ? b - GE0 : b) * 256 + tid;
        float w = 0.f;
        if (e < bp.E) {
            int s = bp.edges[e], d = bp.edges[bp.E + e];
            w = bp.mat[s * bp.N + d];
            int pos = atomicAdd(bp.cnt + d, 1);
            if (pos < BUCK) {
                bp.esrc[d * BUCK + pos] = s;
                bp.eew[d * BUCK + pos] = w;
            }
            atomicAdd(bp.degw + d, w);
        }
        float ws = w;
        #pragma unroll
        for (int o = 16; o; o >>= 1) ws += __shfl_down_sync(FULL, ws, o);
        if (lane == 0 && ws != 0.f) atomicAdd(bp.ewsum, ws);
    } else if (b < GEDGE + GTILE) {
        int t = b - GEDGE;
        int br = t >= GT0;
        const BP& bp = P.b[br];
        gemm_tile(sA, tid, bp.x, bp.gw1, bp.h, bp.N, 128, (br ? t - GT0 : t) << 4, 0, false);
    } else {
        int gw = (b - GEDGE - GTILE) * 8 + wid;
        for (int tt = gw; tt < NPREP; tt += GPREP * 8) prep_warp(P, tt, lane);
    }
}

// ============ K2/K6: block-per-node GCN gather (+fused an dots on pass 0) ============
__global__ void k_gather(Pair P, int which) {
    __shared__ int ssrc[BUCK];
    __shared__ float snorm[BUCK];
    __shared__ float sf[128];
    int task = blockIdx.x;
    int br = task >= P.b[0].N;
    const BP& bp = P.b[br];
    int d = br ? task - P.b[0].N : task;
    int j = threadIdx.x;
    const float* bias = which ? bp.gb2 : bp.gb1;
    float* out = which ? bp.f2 : bp.f1;
    const float* h = bp.h;
    float dd = rsqrtf(bp.degw[d] + 1.0f);
    int deg = min(bp.cnt[d], BUCK);
    if (j < deg) {
        int s = bp.esrc[d * BUCK + j];
        ssrc[j] = s;
        snorm[j] = rsqrtf(bp.degw[s] + 1.0f) * bp.eew[d * BUCK + j] * dd;
    }
    __syncthreads();
    float acc = fmaf(h[d * D + j], dd * dd, bias[j]);
    #pragma unroll 4
    for (int t = 0; t < deg; t++)
        acc = fmaf(h[ssrc[t] * D + j], snorm[t], acc);
    float v = fmaxf(acc, 0.f);
    out[d * D + j] = v;
    if (which == 0) {
        sf[j] = v;
        __syncthreads();
        int wid = j >> 5, lane = j & 31;
        #pragma unroll
        for (int q = 0; q < 2; q++) {
            int hh = wid + q * 4;
            float s1 = 0.f, s2 = 0.f;
            #pragma unroll
            for (int jj = lane; jj < 128; jj += 32) {
                float f = sf[jj];
                s1 = fmaf(f, bp.vsrc[hh * D + jj], s1);
                s2 = fmaf(f, bp.vdst[hh * D + jj], s2);
            }
            s1 = wsum(s1); s2 = wsum(s2);
            if (lane == 0) { bp.an_src[d * H + hh] = s1; bp.an_dst[d * H + hh] = s2; }
        }
    }
}

// ============ K3: fused GAT in f1-space -> g[N,1024] ============
#define GCH (BUCK + 8)
__global__ void k_gat(Pair P) {
    __shared__ int ssrc[GCH];
    __shared__ float sew[GCH];
    __shared__ float scoef[8][GCH];
    __shared__ float sc[8];
    int task = blockIdx.x;
    int br = task >= P.b[0].N;
    const BP& bp = P.b[br];
    int d = br ? task - P.b[0].N : task;
    int tid = threadIdx.x, lane = tid & 31, wid = tid >> 5;   // 128 threads
    if (tid < 8) sc[tid] = bp.cvec[tid];
    float meanw = bp.ewsum[0] / (float)bp.E;
    int deg = min(bp.cnt[d], BUCK);
    int total = deg + 1;
    for (int c = tid; c < total; c += 128) {
        if (c < deg) {
            ssrc[c] = bp.esrc[d * BUCK + c];
            sew[c] = bp.eew[d * BUCK + c];
        } else { ssrc[c] = d; sew[c] = meanw; }
    }
    __syncthreads();
    #pragma unroll
    for (int q = 0; q < 2; q++) {
        int hh = wid + q * 4;
        float adst = bp.an_dst[d * H + hh];
        float chh = sc[hh];
        float m = -INFINITY;
        for (int c = lane; c < total; c += 32) {
            float l = bp.an_src[ssrc[c] * H + hh] + adst + sew[c] * chh;
            l = (l >= 0.f) ? l : 0.2f * l;
            scoef[hh][c] = l;
            m = fmaxf(m, l);
        }
        #pragma unroll
        for (int o = 16; o; o >>= 1) m = fmaxf(m, __shfl_xor_sync(FULL, m, o));
        float den = 0.f;
        for (int c = lane; c < total; c += 32) den += __expf(scoef[hh][c] - m);
        #pragma unroll
        for (int o = 16; o; o >>= 1) den += __shfl_xor_sync(FULL, den, o);
        float inv = 1.f / (den + 1e-16f);
        for (int c = lane; c < total; c += 32)
            scoef[hh][c] = __expf(scoef[hh][c] - m) * inv;
    }
    __syncthreads();
    int j = tid;
    float acc[8] = {0.f, 0.f, 0.f, 0.f, 0.f, 0.f, 0.f, 0.f};
    for (int c = 0; c < total; c++) {
        float v = bp.f1[ssrc[c] * D + j];
        #pragma unroll
        for (int hh = 0; hh < H; hh++)
            acc[hh] = fmaf(v, scoef[hh][c], acc[hh]);
    }
    #pragma unroll
    for (int hh = 0; hh < H; hh++)
        bp.g[d * HD + hh * D + j] = acc[hh];
}

// ============ K4: split-K x32 att_pre += g[:,kb] @ W_eff[kb]  (1376 blocks) ============
__global__ void k_attsplit(Pair P) {
    __shared__ __align__(16) float sA[512];
    int tid = threadIdx.x;
    int b = blockIdx.x;           // b = t*32 + kb
    int t = b >> 5, kb = b & 31;  // kb: 32-deep K chunk
    int br = t >= GT0;
    const BP& bp = P.b[br];
    int rb = (br ? t - GT0 : t) << 4;
    #pragma unroll
    for (int q = 0; q < 2; q++) {
        int idx = q * 256 + tid;
        int r = idx >> 5, k = idx & 31;
        sA[idx] = (rb + r < bp.N) ? bp.g[(rb + r) * HD + kb * 32 + k] : 0.f;
    }
    __syncthreads();
    int col = tid & 127;
    int r0 = (tid >> 7) << 3;
    const float4* sA4 = (const float4*)sA;       // sA[r*32+k] -> sA4[r*8+k4]
    float acc[8] = {0.f, 0.f, 0.f, 0.f, 0.f, 0.f, 0.f, 0.f};
    const float* w = bp.weff + kb * 32 * 128;    // rows kb*32..kb*32+31, col-major rows
    #pragma unroll
    for (int k4 = 0; k4 < 8; k4++) {
        float w0 = w[(k4 * 4 + 0) * 128 + col];
        float w1 = w[(k4 * 4 + 1) * 128 + col];
        float w2 = w[(k4 * 4 + 2) * 128 + col];
        float w3 = w[(k4 * 4 + 3) * 128 + col];
        #pragma unroll
        for (int r = 0; r < 8; r++) {
            float4 a = sA4[(r0 + r) * 8 + k4];
            acc[r] = fmaf(a.x, w0, fmaf(a.y, w1, fmaf(a.z, w2, fmaf(a.w, w3, acc[r]))));
        }
    }
    if (kb == 0) {
        float bo = bp.ab[col];
        #pragma unroll
        for (int r = 0; r < 8; r++) acc[r] += bo;
    }
    #pragma unroll
    for (int r = 0; r < 8; r++)
        if (rb + r0 + r < bp.N) atomicAdd(&bp.att[(rb + r0 + r) * 128 + col], acc[r]);
}

// ============ K5: GEMM3 (h = relu(att_pre)@gw2), relu folded into A load ============
__global__ void k_gemm3(Pair P) {
    __shared__ __align__(16) float sA[2048];
    int tid = threadIdx.x;
    int t = blockIdx.x;
    int br = t >= GT0;
    const BP& bp = P.b[br];
    gemm_tile(sA, tid, bp.att, bp.gw2, bp.h, bp.N, 128, (br ? t - GT0 : t) << 4, 0, true);
}

// ============ K7: CNN head (float4 both sides) ============
__global__ void k_cnn(Pair P) {
    __shared__ __align__(16) float sA[16 * 256];
    int b = blockIdx.x;
    int t = b >> 1, ch = b & 1;
    int br = t >= GT0;
    const BP& bp = P.b[br];
    int rb = (br ? t - GT0 : t) << 4;
    for (int idx = threadIdx.x; idx < 16 * 128; idx += 128) {
        int r = idx >> 7, k = idx & 127;
        int n = rb + r;
        sA[r * 256 + k] = (n < bp.N) ? bp.f1[n * D + k] : 0.f;
        sA[r * 256 + 128 + k] = (n < bp.N) ? bp.f2[n * D + k] : 0.f;
    }
    __syncthreads();
    int o = ch * 128 + threadIdx.x;
    float bo = bp.cb[o];
    float acc[16];
    #pragma unroll
    for (int r = 0; r < 16; r++) acc[r] = bo;
    const float4* w4 = (const float4*)(bp.cw + o * 256);
    const float4* sA4 = (const float4*)sA;
    #pragma unroll 4
    for (int k4 = 0; k4 < 64; k4++) {
        float4 wv = w4[k4];
        #pragma unroll
        for (int r = 0; r < 16; r++) {
            float4 a = sA4[r * 64 + k4];
            acc[r] = fmaf(a.x, wv.x, fmaf(a.y, wv.y, fmaf(a.z, wv.z, fmaf(a.w, wv.w, acc[r]))));
        }
    }
    #pragma unroll
    for (int r = 0; r < 16; r++)
        if (rb + r < bp.N) bp.fea[(rb + r) * 256 + o] = acc[r];
}

// ============ K8: final matmul + state resets (float4 both sides) ============
__global__ void k_final(Pair P, float* __restrict__ out) {
    __shared__ __align__(16) float sA[16 * 256];
    int tid = threadIdx.x;
    int t = blockIdx.x;
    if (t >= GT0) {
        int rid = t - GT0;
        float4 z4 = {0.f, 0.f, 0.f, 0.f};
        float4* a0 = (float4*)P.b[0].att;   // 74880/4 = 18720
        float4* a1 = (float4*)P.b[1].att;   // 11264/4 = 2816
        for (int i = rid * 128 + tid; i < 18720; i += RB * 128) a0[i] = z4;
        for (int i = rid * 128 + tid; i < 2816;  i += RB * 128) a1[i] = z4;
        int idx = rid * 128 + tid;
        if (idx < NCIR) { P.b[0].degw[idx] = 0.f; P.b[0].cnt[idx] = 0; }
        if (idx < NDIS) { P.b[1].degw[idx] = 0.f; P.b[1].cnt[idx] = 0; }
        if (idx == 0) { P.b[0].ewsum[0] = 0.f; P.b[1].ewsum[0] = 0.f; }
        return;
    }
    const float* cir = P.b[0].fea;
    const float* dis = P.b[1].fea;
    int ib = t * 16;
    for (int idx = tid; idx < 16 * 256; idx += 128) {
        int i = ib + (idx >> 8);
        sA[idx] = (i < NCIR) ? cir[i * 256 + (idx & 255)] : 0.f;
    }
    __syncthreads();
    int j = tid;
    if (j >= NDIS) return;
    float acc[16];
    #pragma unroll
    for (int r = 0; r < 16; r++) acc[r] = 0.f;
    const float4* dr4 = (const float4*)(dis + j * 256);
    const float4* sA4 = (const float4*)sA;
    #pragma unroll 4
    for (int k4 = 0; k4 < 64; k4++) {
        float4 dv = dr4[k4];
        #pragma unroll
        for (int r = 0; r < 16; r++) {
            float4 a = sA4[r * 64 + k4];
            acc[r] = fmaf(a.x, dv.x, fmaf(a.y, dv.y, fmaf(a.z, dv.z, fmaf(a.w, dv.w, acc[r]))));
        }
    }
    #pragma unroll
    for (int r = 0; r < 16; r++)
        if (ib + r < NCIR) out[(ib + r) * NDIS + j] = acc[r];
}

// -------------------- host --------------------
static void fill_bp(BP& bp, const float* x, const float* mat, const int* edges,
                    const float* gw1, const float* gb1,
                    const float* aw, const float* asrc, const float* adst,
                    const float* aedge, const float* awe, const float* ab,
                    const float* gw2, const float* gb2,
                    const float* cw, const float* cb,
                    float* fea, int N, int E, float*& S) {
    bp.x = x; bp.mat = mat; bp.edges = edges;
    bp.gw1 = gw1; bp.gb1 = gb1; bp.aw = aw;
    bp.asrc = asrc; bp.adst = adst; bp.aedge = aedge;
    bp.awe = awe; bp.ab = ab; bp.gw2 = gw2; bp.gb2 = gb2;
    bp.cw = cw; bp.cb = cb;
    bp.fea = fea; bp.N = N; bp.E = E;
    bp.degw = S;      S += pad4(N);
    bp.h = S;         S += pad4(N * D);
    bp.f1 = S;        S += pad4(N * D);
    bp.g = S;         S += pad4(N * HD);
    bp.an_src = S;    S += pad4(N * H);
    bp.an_dst = S;    S += pad4(N * H);
    bp.att = S;       S += pad4(N * D);
    bp.f2 = S;        S += pad4(N * D);
    bp.vsrc = S;      S += HD;
    bp.vdst = S;      S += HD;
    bp.cvec = S;      S += 8;
    bp.ewsum = S;     S += 8;
    bp.weff = S;      S += HD * 128;
    bp.eew = S;       S += pad4(N * BUCK);
    bp.cnt = (int*)S;    S += pad4(N);
    bp.esrc = (int*)S;   S += pad4(N * BUCK);
}

extern "C" void kernel_launch(void* const* d_in, const int* in_sizes, int n_in,
                              void* d_out, int out_size) {
    float* S = nullptr;
    cudaGetSymbolAddress((void**)&S, g_scratch);

    const float* in_f[28];
    for (int i = 0; i < 28; i++) in_f[i] = (const float*)d_in[i];
    const int* cc_edges = (const int*)d_in[28];
    const int* dd_edges = (const int*)d_in[29];

    float* out = (float*)d_out;
    float* cirfea = out + NCIR * NDIS;
    float* disfea = cirfea + NCIR * 256;

    Pair P;
    float* cur = S;
    fill_bp(P.b[0], in_f[0], in_f[2], cc_edges,
            in_f[4], in_f[5], in_f[6], in_f[7], in_f[8], in_f[9], in_f[10], in_f[11],
            in_f[12], in_f[13], in_f[24], in_f[25], cirfea, NCIR, ECC, cur);
    fill_bp(P.b[1], in_f[1], in_f[3], dd_edges,
            in_f[14], in_f[15], in_f[16], in_f[17], in_f[18], in_f[19], in_f[20], in_f[21],
            in_f[22], in_f[23], in_f[26], in_f[27], disfea, NDIS, EDD, cur);

    k_phase1<<<GEDGE + GTILE + GPREP, 256>>>(P);
    k_gather<<<NT, 128>>>(P, 0);
    k_gat<<<NT, 128>>>(P);
    k_attsplit<<<GTILE * 32, 256>>>(P);
    k_gemm3<<<GTILE, 256>>>(P);
    k_gather<<<NT, 128>>>(P, 1);
    k_cnn<<<GTILE * 2, 128>>>(P);
    k_final<<<GT0 + RB, 128>>>(P, out);
}

// round 16
// speedup vs baseline: 1.0235x; 1.0235x over previous
#include <cuda_runtime.h>
#include <math.h>

#define D 128
#define HD 1024
#define H 8
#define NCIR 585
#define NDIS 88
#define ECC 20000
#define EDD 3000
#define BUCK 128
#define GE0 79
#define GE1 12
#define GEDGE (GE0 + GE1)   // 91
#define GT0 37
#define GT1 6
#define GTILE (GT0 + GT1)   // 43
#define GPREP 86
#define RB 54               // reset blocks in k_final
#define NT (NCIR + NDIS)    // 673
#define NPREP 6160          // 4096 va + 16 cvec + 2048 weff
#define FULL 0xffffffffu

__device__ __align__(16) float g_scratch[1600000];

struct BP {
    const float *x, *mat;
    const int *edges;
    const float *gb1, *ab, *gb2, *cw, *cb;
    const float *asrc, *adst, *aedge, *awe;
    const float *gw1, *aw, *gw2;
    float *fea;
    int N, E;
    float *degw, *h, *f1, *g, *an_src, *an_dst, *att, *f2, *cvec, *ewsum;
    float *vsrc, *vdst, *weff, *eew;
    int *cnt, *esrc;
};
struct Pair { BP b[2]; };

static inline int pad4(int n) { return (n + 3) & ~3; }

__device__ __forceinline__ float4 ld4(const float* p) { return *(const float4*)p; }
__device__ __forceinline__ float wsum(float v) {
    #pragma unroll
    for (int o = 16; o; o >>= 1) v += __shfl_xor_sync(FULL, v, o);
    return v;
}

// ---- GEMM tile (K=128): C[rb:rb+16, cb:cb+128] = A[*,128] @ W[128,ncols] ----
__device__ void gemm_tile(float* sA, int tid, const float* __restrict__ A,
                          const float* __restrict__ W, float* __restrict__ C,
                          int M, int ncols, int rb, int cb, bool reluA) {
    #pragma unroll
    for (int q = 0; q < 8; q++) {
        int idx = q * 256 + tid;
        int r = idx >> 7, k = idx & 127;
        float v = (rb + r < M) ? A[(rb + r) * 128 + k] : 0.f;
        sA[idx] = reluA ? fmaxf(v, 0.f) : v;
    }
    __syncthreads();
    int col = cb + (tid & 127);
    int r0 = (tid >> 7) << 3;
    const float4* sA4 = (const float4*)sA;
    float acc[8] = {0.f, 0.f, 0.f, 0.f, 0.f, 0.f, 0.f, 0.f};
    #pragma unroll 4
    for (int k4 = 0; k4 < 32; k4++) {
        float w0 = W[(k4 * 4 + 0) * ncols + col];
        float w1 = W[(k4 * 4 + 1) * ncols + col];
        float w2 = W[(k4 * 4 + 2) * ncols + col];
        float w3 = W[(k4 * 4 + 3) * ncols + col];
        #pragma unroll
        for (int r = 0; r < 8; r++) {
            float4 a = sA4[(r0 + r) * 32 + k4];
            acc[r] = fmaf(a.x, w0, fmaf(a.y, w1, fmaf(a.z, w2, fmaf(a.w, w3, acc[r]))));
        }
    }
    #pragma unroll
    for (int r = 0; r < 8; r++)
        if (rb + r0 + r < M) C[(rb + r0 + r) * ncols + col] = acc[r];
}

// ---- prep warp tasks: va dots | cvec | W_eff build (column-major, coalesced) ----
__device__ void prep_warp(const Pair& P, int tt, int lane) {
    if (tt < 4096) {
        int br = tt >> 11; int r = tt & 2047;
        int type = r >> 10; r &= 1023;
        int hh = r >> 7; int k = r & 127;
        const BP& bp = P.b[br];
        const float* avec = type ? bp.adst : bp.asrc;
        float* vout = type ? bp.vdst : bp.vsrc;
        float4 w4 = ld4(bp.aw + k * HD + hh * D + lane * 4);
        float4 a4 = ld4(avec + hh * D + lane * 4);
        float s = wsum(w4.x * a4.x + w4.y * a4.y + w4.z * a4.z + w4.w * a4.w);
        if (lane == 0) vout[hh * D + k] = s;
    } else if (tt < 4112) {
        int r = tt - 4096;
        int br = r >> 3; int hh = r & 7;
        const BP& bp = P.b[br];
        float4 a = ld4(bp.awe + hh * D + lane * 4);
        float4 e = ld4(bp.aedge + hh * D + lane * 4);
        float s = wsum(a.x * e.x + a.y * e.y + a.z * e.z + a.w * e.w);
        if (lane == 0) bp.cvec[hh] = s;
    } else {
        int r = tt - 4112;                 // 0..2047
        int br = r >> 10; r &= 1023;
        int hh = r >> 7; int k = r & 127;
        const BP& bp = P.b[br];
        float4 v = ld4(bp.aw + k * HD + hh * D + lane * 4);
        v.x *= 0.125f; v.y *= 0.125f; v.z *= 0.125f; v.w *= 0.125f;
        ((float4*)(bp.weff + (hh * 128 + k) * 128))[lane] = v;
    }
}

// ============ K1: edge->buckets/deg/ewsum || GEMM1 || prep ============
__global__ void k_phase1(Pair P) {
    __shared__ __align__(16) float sA[2048];
    int tid = threadIdx.x, lane = tid & 31, wid = tid >> 5;
    int b = blockIdx.x;
    if (b < GEDGE) {
        int br = b >= GE0;
        const BP& bp = P.b[br];
        int e = (br ? b - GE0 : b) * 256 + tid;
        float w = 0.f;
        if (e < bp.E) {
            int s = bp.edges[e], d = bp.edges[bp.E + e];
            w = bp.mat[s * bp.N + d];
            int pos = atomicAdd(bp.cnt + d, 1);
            if (pos < BUCK) {
                bp.esrc[d * BUCK + pos] = s;
                bp.eew[d * BUCK + pos] = w;
            }
            atomicAdd(bp.degw + d, w);
        }
        float ws = w;
        #pragma unroll
        for (int o = 16; o; o >>= 1) ws += __shfl_down_sync(FULL, ws, o);
        if (lane == 0 && ws != 0.f) atomicAdd(bp.ewsum, ws);
    } else if (b < GEDGE + GTILE) {
        int t = b - GEDGE;
        int br = t >= GT0;
        const BP& bp = P.b[br];
        gemm_tile(sA, tid, bp.x, bp.gw1, bp.h, bp.N, 128, (br ? t - GT0 : t) << 4, 0, false);
    } else {
        int gw = (b - GEDGE - GTILE) * 8 + wid;
        for (int tt = gw; tt < NPREP; tt += GPREP * 8) prep_warp(P, tt, lane);
    }
}

// ============ K2/K6: block-per-node GCN gather (+fused an dots on pass 0) ============
__global__ void k_gather(Pair P, int which) {
    __shared__ int ssrc[BUCK];
    __shared__ float snorm[BUCK];
    __shared__ float sf[128];
    int task = blockIdx.x;
    int br = task >= P.b[0].N;
    const BP& bp = P.b[br];
    int d = br ? task - P.b[0].N : task;
    int j = threadIdx.x;
    const float* bias = which ? bp.gb2 : bp.gb1;
    float* out = which ? bp.f2 : bp.f1;
    const float* h = bp.h;
    float dd = rsqrtf(bp.degw[d] + 1.0f);
    int deg = min(bp.cnt[d], BUCK);
    if (j < deg) {
        int s = bp.esrc[d * BUCK + j];
        ssrc[j] = s;
        snorm[j] = rsqrtf(bp.degw[s] + 1.0f) * bp.eew[d * BUCK + j] * dd;
    }
    __syncthreads();
    float acc = fmaf(h[d * D + j], dd * dd, bias[j]);
    #pragma unroll 4
    for (int t = 0; t < deg; t++)
        acc = fmaf(h[ssrc[t] * D + j], snorm[t], acc);
    float v = fmaxf(acc, 0.f);
    out[d * D + j] = v;
    if (which == 0) {
        sf[j] = v;
        __syncthreads();
        int wid = j >> 5, lane = j & 31;
        #pragma unroll
        for (int q = 0; q < 2; q++) {
            int hh = wid + q * 4;
            float s1 = 0.f, s2 = 0.f;
            #pragma unroll
            for (int jj = lane; jj < 128; jj += 32) {
                float f = sf[jj];
                s1 = fmaf(f, bp.vsrc[hh * D + jj], s1);
                s2 = fmaf(f, bp.vdst[hh * D + jj], s2);
            }
            s1 = wsum(s1); s2 = wsum(s2);
            if (lane == 0) { bp.an_src[d * H + hh] = s1; bp.an_dst[d * H + hh] = s2; }
        }
    }
}

// ============ K3: fused GAT in f1-space -> g[N,1024], scoef c-major [c][8] ============
#define GCH (BUCK + 8)
__global__ void k_gat(Pair P) {
    __shared__ int ssrc[GCH];
    __shared__ float sew[GCH];
    __shared__ __align__(16) float scoef[GCH * 8];   // [c][hh]
    __shared__ float sc[8];
    int task = blockIdx.x;
    int br = task >= P.b[0].N;
    const BP& bp = P.b[br];
    int d = br ? task - P.b[0].N : task;
    int tid = threadIdx.x, lane = tid & 31, wid = tid >> 5;   // 128 threads
    if (tid < 8) sc[tid] = bp.cvec[tid];
    float meanw = bp.ewsum[0] / (float)bp.E;
    int deg = min(bp.cnt[d], BUCK);
    int total = deg + 1;
    for (int c = tid; c < total; c += 128) {
        if (c < deg) {
            ssrc[c] = bp.esrc[d * BUCK + c];
            sew[c] = bp.eew[d * BUCK + c];
        } else { ssrc[c] = d; sew[c] = meanw; }
    }
    __syncthreads();
    #pragma unroll
    for (int q = 0; q < 2; q++) {
        int hh = wid + q * 4;
        float adst = bp.an_dst[d * H + hh];
        float chh = sc[hh];
        float m = -INFINITY;
        for (int c = lane; c < total; c += 32) {
            float l = bp.an_src[ssrc[c] * H + hh] + adst + sew[c] * chh;
            l = (l >= 0.f) ? l : 0.2f * l;
            scoef[c * 8 + hh] = l;
            m = fmaxf(m, l);
        }
        #pragma unroll
        for (int o = 16; o; o >>= 1) m = fmaxf(m, __shfl_xor_sync(FULL, m, o));
        float den = 0.f;
        for (int c = lane; c < total; c += 32) den += __expf(scoef[c * 8 + hh] - m);
        #pragma unroll
        for (int o = 16; o; o >>= 1) den += __shfl_xor_sync(FULL, den, o);
        float inv = 1.f / (den + 1e-16f);
        for (int c = lane; c < total; c += 32)
            scoef[c * 8 + hh] = __expf(scoef[c * 8 + hh] - m) * inv;
    }
    __syncthreads();
    int j = tid;
    float acc[8] = {0.f, 0.f, 0.f, 0.f, 0.f, 0.f, 0.f, 0.f};
    const float4* sc4 = (const float4*)scoef;
    for (int c = 0; c < total; c++) {
        float v = bp.f1[ssrc[c] * D + j];
        float4 c0 = sc4[c * 2];
        float4 c1 = sc4[c * 2 + 1];
        acc[0] = fmaf(v, c0.x, acc[0]); acc[1] = fmaf(v, c0.y, acc[1]);
        acc[2] = fmaf(v, c0.z, acc[2]); acc[3] = fmaf(v, c0.w, acc[3]);
        acc[4] = fmaf(v, c1.x, acc[4]); acc[5] = fmaf(v, c1.y, acc[5]);
        acc[6] = fmaf(v, c1.z, acc[6]); acc[7] = fmaf(v, c1.w, acc[7]);
    }
    #pragma unroll
    for (int hh = 0; hh < H; hh++)
        bp.g[d * HD + hh * D + j] = acc[hh];
}

// ============ K4: split-K x16 att_pre += g[:,kb] @ W_eff[kb]  (688 blocks) ============
__global__ void k_attsplit(Pair P) {
    __shared__ __align__(16) float sA[1024];
    int tid = threadIdx.x;
    int b = blockIdx.x;           // b = t*16 + kb
    int t = b >> 4, kb = b & 15;  // kb: 64-deep K chunk
    int br = t >= GT0;
    const BP& bp = P.b[br];
    int rb = (br ? t - GT0 : t) << 4;
    #pragma unroll
    for (int q = 0; q < 4; q++) {
        int idx = q * 256 + tid;
        int r = idx >> 6, k = idx & 63;
        sA[idx] = (rb + r < bp.N) ? bp.g[(rb + r) * HD + kb * 64 + k] : 0.f;
    }
    __syncthreads();
    int col = tid & 127;
    int r0 = (tid >> 7) << 3;
    const float4* sA4 = (const float4*)sA;
    float acc[8] = {0.f, 0.f, 0.f, 0.f, 0.f, 0.f, 0.f, 0.f};
    const float* w = bp.weff + kb * 64 * 128;
    #pragma unroll 4
    for (int k4 = 0; k4 < 16; k4++) {
        float w0 = w[(k4 * 4 + 0) * 128 + col];
        float w1 = w[(k4 * 4 + 1) * 128 + col];
        float w2 = w[(k4 * 4 + 2) * 128 + col];
        float w3 = w[(k4 * 4 + 3) * 128 + col];
        #pragma unroll
        for (int r = 0; r < 8; r++) {
            float4 a = sA4[(r0 + r) * 16 + k4];
            acc[r] = fmaf(a.x, w0, fmaf(a.y, w1, fmaf(a.z, w2, fmaf(a.w, w3, acc[r]))));
        }
    }
    if (kb == 0) {
        float bo = bp.ab[col];
        #pragma unroll
        for (int r = 0; r < 8; r++) acc[r] += bo;
    }
    #pragma unroll
    for (int r = 0; r < 8; r++)
        if (rb + r0 + r < bp.N) atomicAdd(&bp.att[(rb + r0 + r) * 128 + col], acc[r]);
}

// ============ K5: GEMM3 (h = relu(att_pre)@gw2), relu folded into A load ============
__global__ void k_gemm3(Pair P) {
    __shared__ __align__(16) float sA[2048];
    int tid = threadIdx.x;
    int t = blockIdx.x;
    int br = t >= GT0;
    const BP& bp = P.b[br];
    gemm_tile(sA, tid, bp.att, bp.gw2, bp.h, bp.N, 128, (br ? t - GT0 : t) << 4, 0, true);
}

// ============ K7: CNN head (float4 both sides) ============
__global__ void k_cnn(Pair P) {
    __shared__ __align__(16) float sA[16 * 256];
    int b = blockIdx.x;
    int t = b >> 1, ch = b & 1;
    int br = t >= GT0;
    const BP& bp = P.b[br];
    int rb = (br ? t - GT0 : t) << 4;
    for (int idx = threadIdx.x; idx < 16 * 128; idx += 128) {
        int r = idx >> 7, k = idx & 127;
        int n = rb + r;
        sA[r * 256 + k] = (n < bp.N) ? bp.f1[n * D + k] : 0.f;
        sA[r * 256 + 128 + k] = (n < bp.N) ? bp.f2[n * D + k] : 0.f;
    }
    __syncthreads();
    int o = ch * 128 + threadIdx.x;
    float bo = bp.cb[o];
    float acc[16];
    #pragma unroll
    for (int r = 0; r < 16; r++) acc[r] = bo;
    const float4* w4 = (const float4*)(bp.cw + o * 256);
    const float4* sA4 = (const float4*)sA;
    #pragma unroll 4
    for (int k4 = 0; k4 < 64; k4++) {
        float4 wv = w4[k4];
        #pragma unroll
        for (int r = 0; r < 16; r++) {
            float4 a = sA4[r * 64 + k4];
            acc[r] = fmaf(a.x, wv.x, fmaf(a.y, wv.y, fmaf(a.z, wv.z, fmaf(a.w, wv.w, acc[r]))));
        }
    }
    #pragma unroll
    for (int r = 0; r < 16; r++)
        if (rb + r < bp.N) bp.fea[(rb + r) * 256 + o] = acc[r];
}

// ============ K8: final matmul + state resets (float4 both sides) ============
__global__ void k_final(Pair P, float* __restrict__ out) {
    __shared__ __align__(16) float sA[16 * 256];
    int tid = threadIdx.x;
    int t = blockIdx.x;
    if (t >= GT0) {
        int rid = t - GT0;
        float4 z4 = {0.f, 0.f, 0.f, 0.f};
        float4* a0 = (float4*)P.b[0].att;   // 74880/4 = 18720
        float4* a1 = (float4*)P.b[1].att;   // 11264/4 = 2816
        for (int i = rid * 128 + tid; i < 18720; i += RB * 128) a0[i] = z4;
        for (int i = rid * 128 + tid; i < 2816;  i += RB * 128) a1[i] = z4;
        int idx = rid * 128 + tid;
        if (idx < NCIR) { P.b[0].degw[idx] = 0.f; P.b[0].cnt[idx] = 0; }
        if (idx < NDIS) { P.b[1].degw[idx] = 0.f; P.b[1].cnt[idx] = 0; }
        if (idx == 0) { P.b[0].ewsum[0] = 0.f; P.b[1].ewsum[0] = 0.f; }
        return;
    }
    const float* cir = P.b[0].fea;
    const float* dis = P.b[1].fea;
    int ib = t * 16;
    for (int idx = tid; idx < 16 * 256; idx += 128) {
        int i = ib + (idx >> 8);
        sA[idx] = (i < NCIR) ? cir[i * 256 + (idx & 255)] : 0.f;
    }
    __syncthreads();
    int j = tid;
    if (j >= NDIS) return;
    float acc[16];
    #pragma unroll
    for (int r = 0; r < 16; r++) acc[r] = 0.f;
    const float4* dr4 = (const float4*)(dis + j * 256);
    const float4* sA4 = (const float4*)sA;
    #pragma unroll 4
    for (int k4 = 0; k4 < 64; k4++) {
        float4 dv = dr4[k4];
        #pragma unroll
        for (int r = 0; r < 16; r++) {
            float4 a = sA4[r * 64 + k4];
            acc[r] = fmaf(a.x, dv.x, fmaf(a.y, dv.y, fmaf(a.z, dv.z, fmaf(a.w, dv.w, acc[r]))));
        }
    }
    #pragma unroll
    for (int r = 0; r < 16; r++)
        if (ib + r < NCIR) out[(ib + r) * NDIS + j] = acc[r];
}

// -------------------- host --------------------
static void fill_bp(BP& bp, const float* x, const float* mat, const int* edges,
                    const float* gw1, const float* gb1,
                    const float* aw, const float* asrc, const float* adst,
                    const float* aedge, const float* awe, const float* ab,
                    const float* gw2, const float* gb2,
                    const float* cw, const float* cb,
                    float* fea, int N, int E, float*& S) {
    bp.x = x; bp.mat = mat; bp.edges = edges;
    bp.gw1 = gw1; bp.gb1 = gb1; bp.aw = aw;
    bp.asrc = asrc; bp.adst = adst; bp.aedge = aedge;
    bp.awe = awe; bp.ab = ab; bp.gw2 = gw2; bp.gb2 = gb2;
    bp.cw = cw; bp.cb = cb;
    bp.fea = fea; bp.N = N; bp.E = E;
    bp.degw = S;      S += pad4(N);
    bp.h = S;         S += pad4(N * D);
    bp.f1 = S;        S += pad4(N * D);
    bp.g = S;         S += pad4(N * HD);
    bp.an_src = S;    S += pad4(N * H);
    bp.an_dst = S;    S += pad4(N * H);
    bp.att = S;       S += pad4(N * D);
    bp.f2 = S;        S += pad4(N * D);
    bp.vsrc = S;      S += HD;
    bp.vdst = S;      S += HD;
    bp.cvec = S;      S += 8;
    bp.ewsum = S;     S += 8;
    bp.weff = S;      S += HD * 128;
    bp.eew = S;       S += pad4(N * BUCK);
    bp.cnt = (int*)S;    S += pad4(N);
    bp.esrc = (int*)S;   S += pad4(N * BUCK);
}

extern "C" void kernel_launch(void* const* d_in, const int* in_sizes, int n_in,
                              void* d_out, int out_size) {
    float* S = nullptr;
    cudaGetSymbolAddress((void**)&S, g_scratch);

    const float* in_f[28];
    for (int i = 0; i < 28; i++) in_f[i] = (const float*)d_in[i];
    const int* cc_edges = (const int*)d_in[28];
    const int* dd_edges = (const int*)d_in[29];

    float* out = (float*)d_out;
    float* cirfea = out + NCIR * NDIS;
    float* disfea = cirfea + NCIR * 256;

    Pair P;
    float* cur = S;
    fill_bp(P.b[0], in_f[0], in_f[2], cc_edges,
            in_f[4], in_f[5], in_f[6], in_f[7], in_f[8], in_f[9], in_f[10], in_f[11],
            in_f[12], in_f[13], in_f[24], in_f[25], cirfea, NCIR, ECC, cur);
    fill_bp(P.b[1], in_f[1], in_f[3], dd_edges,
            in_f[14], in_f[15], in_f[16], in_f[17], in_f[18], in_f[19], in_f[20], in_f[21],
            in_f[22], in_f[23], in_f[26], in_f[27], disfea, NDIS, EDD, cur);

    k_phase1<<<GEDGE + GTILE + GPREP, 256>>>(P);
    k_gather<<<NT, 128>>>(P, 0);
    k_gat<<<NT, 128>>>(P);
    k_attsplit<<<GTILE * 16, 256>>>(P);
    k_gemm3<<<GTILE, 256>>>(P);
    k_gather<<<NT, 128>>>(P, 1);
    k_cnn<<<GTILE * 2, 128>>>(P);
    k_final<<<GT0 + RB, 128>>>(P, out);
}

// round 17
// speedup vs baseline: 1.0722x; 1.0476x over previous
#include <cuda_runtime.h>
#include <math.h>

#define D 128
#define HD 1024
#define H 8
#define NCIR 585
#define NDIS 88
#define ECC 20000
#define EDD 3000
#define BUCK 128
#define GE0 79
#define GE1 12
#define GEDGE (GE0 + GE1)   // 91
#define GT0 37
#define GT1 6
#define GTILE (GT0 + GT1)   // 43
#define GPREP 86
#define RB 54               // reset blocks in k_final
#define NT (NCIR + NDIS)    // 673
#define NPREP 6160          // 4096 va + 16 cvec + 2048 weff
#define FULL 0xffffffffu

__device__ __align__(16) float g_scratch[1600000];

struct BP {
    const float *x, *mat;
    const int *edges;
    const float *gb1, *ab, *gb2, *cw, *cb;
    const float *asrc, *adst, *aedge, *awe;
    const float *gw1, *aw, *gw2;
    float *fea;
    int N, E;
    float *degw, *h, *f1, *g, *an_src, *an_dst, *att, *f2, *cvec, *ewsum;
    float *vsrc, *vdst, *weff, *eew;
    int *cnt, *esrc;
};
struct Pair { BP b[2]; };

static inline int pad4(int n) { return (n + 3) & ~3; }

__device__ __forceinline__ float4 ld4(const float* p) { return *(const float4*)p; }
__device__ __forceinline__ float wsum(float v) {
    #pragma unroll
    for (int o = 16; o; o >>= 1) v += __shfl_xor_sync(FULL, v, o);
    return v;
}

// ---- GEMM tile (K=128): C[rb:rb+16, cb:cb+128] = A[*,128] @ W[128,ncols] ----
__device__ void gemm_tile(float* sA, int tid, const float* __restrict__ A,
                          const float* __restrict__ W, float* __restrict__ C,
                          int M, int ncols, int rb, int cb, bool reluA) {
    #pragma unroll
    for (int q = 0; q < 8; q++) {
        int idx = q * 256 + tid;
        int r = idx >> 7, k = idx & 127;
        float v = (rb + r < M) ? A[(rb + r) * 128 + k] : 0.f;
        sA[idx] = reluA ? fmaxf(v, 0.f) : v;
    }
    __syncthreads();
    int col = cb + (tid & 127);
    int r0 = (tid >> 7) << 3;
    const float4* sA4 = (const float4*)sA;
    float acc[8] = {0.f, 0.f, 0.f, 0.f, 0.f, 0.f, 0.f, 0.f};
    #pragma unroll 4
    for (int k4 = 0; k4 < 32; k4++) {
        float w0 = W[(k4 * 4 + 0) * ncols + col];
        float w1 = W[(k4 * 4 + 1) * ncols + col];
        float w2 = W[(k4 * 4 + 2) * ncols + col];
        float w3 = W[(k4 * 4 + 3) * ncols + col];
        #pragma unroll
        for (int r = 0; r < 8; r++) {
            float4 a = sA4[(r0 + r) * 32 + k4];
            acc[r] = fmaf(a.x, w0, fmaf(a.y, w1, fmaf(a.z, w2, fmaf(a.w, w3, acc[r]))));
        }
    }
    #pragma unroll
    for (int r = 0; r < 8; r++)
        if (rb + r0 + r < M) C[(rb + r0 + r) * ncols + col] = acc[r];
}

// ---- prep warp tasks: va dots | cvec | W_eff build (column-major, coalesced) ----
__device__ void prep_warp(const Pair& P, int tt, int lane) {
    if (tt < 4096) {
        int br = tt >> 11; int r = tt & 2047;
        int type = r >> 10; r &= 1023;
        int hh = r >> 7; int k = r & 127;
        const BP& bp = P.b[br];
        const float* avec = type ? bp.adst : bp.asrc;
        float* vout = type ? bp.vdst : bp.vsrc;
        float4 w4 = ld4(bp.aw + k * HD + hh * D + lane * 4);
        float4 a4 = ld4(avec + hh * D + lane * 4);
        float s = wsum(w4.x * a4.x + w4.y * a4.y + w4.z * a4.z + w4.w * a4.w);
        if (lane == 0) vout[hh * D + k] = s;
    } else if (tt < 4112) {
        int r = tt - 4096;
        int br = r >> 3; int hh = r & 7;
        const BP& bp = P.b[br];
        float4 a = ld4(bp.awe + hh * D + lane * 4);
        float4 e = ld4(bp.aedge + hh * D + lane * 4);
        float s = wsum(a.x * e.x + a.y * e.y + a.z * e.z + a.w * e.w);
        if (lane == 0) bp.cvec[hh] = s;
    } else {
        int r = tt - 4112;                 // 0..2047
        int br = r >> 10; r &= 1023;
        int hh = r >> 7; int k = r & 127;
        const BP& bp = P.b[br];
        float4 v = ld4(bp.aw + k * HD + hh * D + lane * 4);
        v.x *= 0.125f; v.y *= 0.125f; v.z *= 0.125f; v.w *= 0.125f;
        ((float4*)(bp.weff + (hh * 128 + k) * 128))[lane] = v;
    }
}

// ============ K1: edge->buckets/deg/ewsum || GEMM1 || prep ============
__global__ void k_phase1(Pair P) {
    __shared__ __align__(16) float sA[2048];
    cudaGridDependencySynchronize();
    int tid = threadIdx.x, lane = tid & 31, wid = tid >> 5;
    int b = blockIdx.x;
    if (b < GEDGE) {
        int br = b >= GE0;
        const BP& bp = P.b[br];
        int e = (br ? b - GE0 : b) * 256 + tid;
        float w = 0.f;
        if (e < bp.E) {
            int s = bp.edges[e], d = bp.edges[bp.E + e];
            w = bp.mat[s * bp.N + d];
            int pos = atomicAdd(bp.cnt + d, 1);
            if (pos < BUCK) {
                bp.esrc[d * BUCK + pos] = s;
                bp.eew[d * BUCK + pos] = w;
            }
            atomicAdd(bp.degw + d, w);
        }
        float ws = w;
        #pragma unroll
        for (int o = 16; o; o >>= 1) ws += __shfl_down_sync(FULL, ws, o);
        if (lane == 0 && ws != 0.f) atomicAdd(bp.ewsum, ws);
    } else if (b < GEDGE + GTILE) {
        int t = b - GEDGE;
        int br = t >= GT0;
        const BP& bp = P.b[br];
        gemm_tile(sA, tid, bp.x, bp.gw1, bp.h, bp.N, 128, (br ? t - GT0 : t) << 4, 0, false);
    } else {
        int gw = (b - GEDGE - GTILE) * 8 + wid;
        for (int tt = gw; tt < NPREP; tt += GPREP * 8) prep_warp(P, tt, lane);
    }
}

// ============ K2/K6: block-per-node GCN gather (+fused an dots on pass 0) ============
__global__ void k_gather(Pair P, int which) {
    __shared__ int ssrc[BUCK];
    __shared__ float snorm[BUCK];
    __shared__ float sf[128];
    cudaGridDependencySynchronize();
    int task = blockIdx.x;
    int br = task >= P.b[0].N;
    const BP& bp = P.b[br];
    int d = br ? task - P.b[0].N : task;
    int j = threadIdx.x;
    const float* bias = which ? bp.gb2 : bp.gb1;
    float* out = which ? bp.f2 : bp.f1;
    const float* h = bp.h;
    float dd = rsqrtf(bp.degw[d] + 1.0f);
    int deg = min(bp.cnt[d], BUCK);
    if (j < deg) {
        int s = bp.esrc[d * BUCK + j];
        ssrc[j] = s;
        snorm[j] = rsqrtf(bp.degw[s] + 1.0f) * bp.eew[d * BUCK + j] * dd;
    }
    __syncthreads();
    float acc = fmaf(h[d * D + j], dd * dd, bias[j]);
    #pragma unroll 4
    for (int t = 0; t < deg; t++)
        acc = fmaf(h[ssrc[t] * D + j], snorm[t], acc);
    float v = fmaxf(acc, 0.f);
    out[d * D + j] = v;
    if (which == 0) {
        sf[j] = v;
        __syncthreads();
        int wid = j >> 5, lane = j & 31;
        #pragma unroll
        for (int q = 0; q < 2; q++) {
            int hh = wid + q * 4;
            float s1 = 0.f, s2 = 0.f;
            #pragma unroll
            for (int jj = lane; jj < 128; jj += 32) {
                float f = sf[jj];
                s1 = fmaf(f, bp.vsrc[hh * D + jj], s1);
                s2 = fmaf(f, bp.vdst[hh * D + jj], s2);
            }
            s1 = wsum(s1); s2 = wsum(s2);
            if (lane == 0) { bp.an_src[d * H + hh] = s1; bp.an_dst[d * H + hh] = s2; }
        }
    }
}

// ============ K3: fused GAT in f1-space -> g[N,1024], scoef c-major [c][8] ============
#define GCH (BUCK + 8)
__global__ void k_gat(Pair P) {
    __shared__ int ssrc[GCH];
    __shared__ float sew[GCH];
    __shared__ __align__(16) float scoef[GCH * 8];   // [c][hh]
    __shared__ float sc[8];
    cudaGridDependencySynchronize();
    int task = blockIdx.x;
    int br = task >= P.b[0].N;
    const BP& bp = P.b[br];
    int d = br ? task - P.b[0].N : task;
    int tid = threadIdx.x, lane = tid & 31, wid = tid >> 5;   // 128 threads
    if (tid < 8) sc[tid] = bp.cvec[tid];
    float meanw = bp.ewsum[0] / (float)bp.E;
    int deg = min(bp.cnt[d], BUCK);
    int total = deg + 1;
    for (int c = tid; c < total; c += 128) {
        if (c < deg) {
            ssrc[c] = bp.esrc[d * BUCK + c];
            sew[c] = bp.eew[d * BUCK + c];
        } else { ssrc[c] = d; sew[c] = meanw; }
    }
    __syncthreads();
    #pragma unroll
    for (int q = 0; q < 2; q++) {
        int hh = wid + q * 4;
        float adst = bp.an_dst[d * H + hh];
        float chh = sc[hh];
        float m = -INFINITY;
        for (int c = lane; c < total; c += 32) {
            float l = bp.an_src[ssrc[c] * H + hh] + adst + sew[c] * chh;
            l = (l >= 0.f) ? l : 0.2f * l;
            scoef[c * 8 + hh] = l;
            m = fmaxf(m, l);
        }
        #pragma unroll
        for (int o = 16; o; o >>= 1) m = fmaxf(m, __shfl_xor_sync(FULL, m, o));
        float den = 0.f;
        for (int c = lane; c < total; c += 32) den += __expf(scoef[c * 8 + hh] - m);
        #pragma unroll
        for (int o = 16; o; o >>= 1) den += __shfl_xor_sync(FULL, den, o);
        float inv = 1.f / (den + 1e-16f);
        for (int c = lane; c < total; c += 32)
            scoef[c * 8 + hh] = __expf(scoef[c * 8 + hh] - m) * inv;
    }
    __syncthreads();
    int j = tid;
    float acc[8] = {0.f, 0.f, 0.f, 0.f, 0.f, 0.f, 0.f, 0.f};
    const float4* sc4 = (const float4*)scoef;
    for (int c = 0; c < total; c++) {
        float v = bp.f1[ssrc[c] * D + j];
        float4 c0 = sc4[c * 2];
        float4 c1 = sc4[c * 2 + 1];
        acc[0] = fmaf(v, c0.x, acc[0]); acc[1] = fmaf(v, c0.y, acc[1]);
        acc[2] = fmaf(v, c0.z, acc[2]); acc[3] = fmaf(v, c0.w, acc[3]);
        acc[4] = fmaf(v, c1.x, acc[4]); acc[5] = fmaf(v, c1.y, acc[5]);
        acc[6] = fmaf(v, c1.z, acc[6]); acc[7] = fmaf(v, c1.w, acc[7]);
    }
    #pragma unroll
    for (int hh = 0; hh < H; hh++)
        bp.g[d * HD + hh * D + j] = acc[hh];
}

// ============ K4: split-K x16 att_pre += g[:,kb] @ W_eff[kb]  (688 blocks) ============
__global__ void k_attsplit(Pair P) {
    __shared__ __align__(16) float sA[1024];
    cudaGridDependencySynchronize();
    int tid = threadIdx.x;
    int b = blockIdx.x;           // b = t*16 + kb
    int t = b >> 4, kb = b & 15;  // kb: 64-deep K chunk
    int br = t >= GT0;
    const BP& bp = P.b[br];
    int rb = (br ? t - GT0 : t) << 4;
    #pragma unroll
    for (int q = 0; q < 4; q++) {
        int idx = q * 256 + tid;
        int r = idx >> 6, k = idx & 63;
        sA[idx] = (rb + r < bp.N) ? bp.g[(rb + r) * HD + kb * 64 + k] : 0.f;
    }
    __syncthreads();
    int col = tid & 127;
    int r0 = (tid >> 7) << 3;
    const float4* sA4 = (const float4*)sA;
    float acc[8] = {0.f, 0.f, 0.f, 0.f, 0.f, 0.f, 0.f, 0.f};
    const float* w = bp.weff + kb * 64 * 128;
    #pragma unroll 4
    for (int k4 = 0; k4 < 16; k4++) {
        float w0 = w[(k4 * 4 + 0) * 128 + col];
        float w1 = w[(k4 * 4 + 1) * 128 + col];
        float w2 = w[(k4 * 4 + 2) * 128 + col];
        float w3 = w[(k4 * 4 + 3) * 128 + col];
        #pragma unroll
        for (int r = 0; r < 8; r++) {
            float4 a = sA4[(r0 + r) * 16 + k4];
            acc[r] = fmaf(a.x, w0, fmaf(a.y, w1, fmaf(a.z, w2, fmaf(a.w, w3, acc[r]))));
        }
    }
    if (kb == 0) {
        float bo = bp.ab[col];
        #pragma unroll
        for (int r = 0; r < 8; r++) acc[r] += bo;
    }
    #pragma unroll
    for (int r = 0; r < 8; r++)
        if (rb + r0 + r < bp.N) atomicAdd(&bp.att[(rb + r0 + r) * 128 + col], acc[r]);
}

// ============ K5: GEMM3 (h = relu(att_pre)@gw2), relu folded into A load ============
__global__ void k_gemm3(Pair P) {
    __shared__ __align__(16) float sA[2048];
    cudaGridDependencySynchronize();
    int tid = threadIdx.x;
    int t = blockIdx.x;
    int br = t >= GT0;
    const BP& bp = P.b[br];
    gemm_tile(sA, tid, bp.att, bp.gw2, bp.h, bp.N, 128, (br ? t - GT0 : t) << 4, 0, true);
}

// ============ K7: CNN head (float4 both sides) ============
__global__ void k_cnn(Pair P) {
    __shared__ __align__(16) float sA[16 * 256];
    cudaGridDependencySynchronize();
    int b = blockIdx.x;
    int t = b >> 1, ch = b & 1;
    int br = t >= GT0;
    const BP& bp = P.b[br];
    int rb = (br ? t - GT0 : t) << 4;
    for (int idx = threadIdx.x; idx < 16 * 128; idx += 128) {
        int r = idx >> 7, k = idx & 127;
        int n = rb + r;
        sA[r * 256 + k] = (n < bp.N) ? bp.f1[n * D + k] : 0.f;
        sA[r * 256 + 128 + k] = (n < bp.N) ? bp.f2[n * D + k] : 0.f;
    }
    __syncthreads();
    int o = ch * 128 + threadIdx.x;
    float bo = bp.cb[o];
    float acc[16];
    #pragma unroll
    for (int r = 0; r < 16; r++) acc[r] = bo;
    const float4* w4 = (const float4*)(bp.cw + o * 256);
    const float4* sA4 = (const float4*)sA;
    #pragma unroll 4
    for (int k4 = 0; k4 < 64; k4++) {
        float4 wv = w4[k4];
        #pragma unroll
        for (int r = 0; r < 16; r++) {
            float4 a = sA4[r * 64 + k4];
            acc[r] = fmaf(a.x, wv.x, fmaf(a.y, wv.y, fmaf(a.z, wv.z, fmaf(a.w, wv.w, acc[r]))));
        }
    }
    #pragma unroll
    for (int r = 0; r < 16; r++)
        if (rb + r < bp.N) bp.fea[(rb + r) * 256 + o] = acc[r];
}

// ============ K8: final matmul + state resets (float4 both sides) ============
__global__ void k_final(Pair P, float* __restrict__ out) {
    __shared__ __align__(16) float sA[16 * 256];
    cudaGridDependencySynchronize();
    int tid = threadIdx.x;
    int t = blockIdx.x;
    if (t >= GT0) {
        int rid = t - GT0;
        float4 z4 = {0.f, 0.f, 0.f, 0.f};
        float4* a0 = (float4*)P.b[0].att;   // 74880/4 = 18720
        float4* a1 = (float4*)P.b[1].att;   // 11264/4 = 2816
        for (int i = rid * 128 + tid; i < 18720; i += RB * 128) a0[i] = z4;
        for (int i = rid * 128 + tid; i < 2816;  i += RB * 128) a1[i] = z4;
        int idx = rid * 128 + tid;
        if (idx < NCIR) { P.b[0].degw[idx] = 0.f; P.b[0].cnt[idx] = 0; }
        if (idx < NDIS) { P.b[1].degw[idx] = 0.f; P.b[1].cnt[idx] = 0; }
        if (idx == 0) { P.b[0].ewsum[0] = 0.f; P.b[1].ewsum[0] = 0.f; }
        return;
    }
    const float* cir = P.b[0].fea;
    const float* dis = P.b[1].fea;
    int ib = t * 16;
    for (int idx = tid; idx < 16 * 256; idx += 128) {
        int i = ib + (idx >> 8);
        sA[idx] = (i < NCIR) ? cir[i * 256 + (idx & 255)] : 0.f;
    }
    __syncthreads();
    int j = tid;
    if (j >= NDIS) return;
    float acc[16];
    #pragma unroll
    for (int r = 0; r < 16; r++) acc[r] = 0.f;
    const float4* dr4 = (const float4*)(dis + j * 256);
    const float4* sA4 = (const float4*)sA;
    #pragma unroll 4
    for (int k4 = 0; k4 < 64; k4++) {
        float4 dv = dr4[k4];
        #pragma unroll
        for (int r = 0; r < 16; r++) {
            float4 a = sA4[r * 64 + k4];
            acc[r] = fmaf(a.x, dv.x, fmaf(a.y, dv.y, fmaf(a.z, dv.z, fmaf(a.w, dv.w, acc[r]))));
        }
    }
    #pragma unroll
    for (int r = 0; r < 16; r++)
        if (ib + r < NCIR) out[(ib + r) * NDIS + j] = acc[r];
}

// -------------------- host --------------------
static void fill_bp(BP& bp, const float* x, const float* mat, const int* edges,
                    const float* gw1, const float* gb1,
                    const float* aw, const float* asrc, const float* adst,
                    const float* aedge, const float* awe, const float* ab,
                    const float* gw2, const float* gb2,
                    const float* cw, const float* cb,
                    float* fea, int N, int E, float*& S) {
    bp.x = x; bp.mat = mat; bp.edges = edges;
    bp.gw1 = gw1; bp.gb1 = gb1; bp.aw = aw;
    bp.asrc = asrc; bp.adst = adst; bp.aedge = aedge;
    bp.awe = awe; bp.ab = ab; bp.gw2 = gw2; bp.gb2 = gb2;
    bp.cw = cw; bp.cb = cb;
    bp.fea = fea; bp.N = N; bp.E = E;
    bp.degw = S;      S += pad4(N);
    bp.h = S;         S += pad4(N * D);
    bp.f1 = S;        S += pad4(N * D);
    bp.g = S;         S += pad4(N * HD);
    bp.an_src = S;    S += pad4(N * H);
    bp.an_dst = S;    S += pad4(N * H);
    bp.att = S;       S += pad4(N * D);
    bp.f2 = S;        S += pad4(N * D);
    bp.vsrc = S;      S += HD;
    bp.vdst = S;      S += HD;
    bp.cvec = S;      S += 8;
    bp.ewsum = S;     S += 8;
    bp.weff = S;      S += HD * 128;
    bp.eew = S;       S += pad4(N * BUCK);
    bp.cnt = (int*)S;    S += pad4(N);
    bp.esrc = (int*)S;   S += pad4(N * BUCK);
}

template <typename K, typename... Args>
static void pdl_launch(K kern, int grid, int block, Args... args) {
    cudaLaunchConfig_t cfg = {};
    cfg.gridDim = dim3(grid);
    cfg.blockDim = dim3(block);
    cfg.stream = 0;
    cudaLaunchAttribute at;
    at.id = cudaLaunchAttributeProgrammaticStreamSerialization;
    at.val.programmaticStreamSerializationAllowed = 1;
    cfg.attrs = &at;
    cfg.numAttrs = 1;
    cudaLaunchKernelEx(&cfg, kern, args...);
}

extern "C" void kernel_launch(void* const* d_in, const int* in_sizes, int n_in,
                              void* d_out, int out_size) {
    float* S = nullptr;
    cudaGetSymbolAddress((void**)&S, g_scratch);

    const float* in_f[28];
    for (int i = 0; i < 28; i++) in_f[i] = (const float*)d_in[i];
    const int* cc_edges = (const int*)d_in[28];
    const int* dd_edges = (const int*)d_in[29];

    float* out = (float*)d_out;
    float* cirfea = out + NCIR * NDIS;
    float* disfea = cirfea + NCIR * 256;

    Pair P;
    float* cur = S;
    fill_bp(P.b[0], in_f[0], in_f[2], cc_edges,
            in_f[4], in_f[5], in_f[6], in_f[7], in_f[8], in_f[9], in_f[10], in_f[11],
            in_f[12], in_f[13], in_f[24], in_f[25], cirfea, NCIR, ECC, cur);
    fill_bp(P.b[1], in_f[1], in_f[3], dd_edges,
            in_f[14], in_f[15], in_f[16], in_f[17], in_f[18], in_f[19], in_f[20], in_f[21],
            in_f[22], in_f[23], in_f[26], in_f[27], disfea, NDIS, EDD, cur);

    pdl_launch(k_phase1, GEDGE + GTILE + GPREP, 256, P);
    pdl_launch(k_gather, NT, 128, P, 0);
    pdl_launch(k_gat, NT, 128, P);
    pdl_launch(k_attsplit, GTILE * 16, 256, P);
    pdl_launch(k_gemm3, GTILE, 256, P);
    pdl_launch(k_gather, NT, 128, P, 1);
    pdl_launch(k_cnn, GTILE * 2, 128, P);
    pdl_launch(k_final, GT0 + RB, 128, P, out);
}